// round 1
// baseline (speedup 1.0000x reference)
#include <cuda_runtime.h>
#include <cstdint>

// TaxaNetLoss: loss = sum_{k=1..3} W[k] * (viol_k * e + ce_k)
//   viol_k = #{ i in [1,N) : H[argm[k-1,i], argm[k,i]] == 0 }
//   ce_k   = mean_i ( log( sum_{j in level k} exp(yp[i,j]) + (C - L_k) ) - yp[i, yt[i,k]] )
//   argm[k,i] = argmax over full C of (yp masked to level k, zeros outside),
//               first-occurrence tie-break (so "first zero index" when in-level max < 0).

#define N_SAMPLES 1024
#define C_TOTAL   13430

static __device__ float g_ce[N_SAMPLES * 4];
static __device__ int   g_argm[N_SAMPLES * 4];

__device__ __forceinline__ float fexp(float x) {
    // Schraudolph fast exp: 1 FFMA + 1 F2I. ~+-3% rel err, fine for the lse sum
    // (CE contributes ~4.8 abs to a ~1400 loss; lse err <= log(1.03)).
    return __int_as_float((int)fmaf(x, 12102203.0f, 1064866805.0f));
}

template <int NT>
__global__ __launch_bounds__(NT) void levels_kernel(
    const float* __restrict__ yp, const int* __restrict__ yt)
{
    const int i   = blockIdx.x;       // sample
    const int tid = threadIdx.x;
    const float* row = yp + (size_t)i * C_TOTAL;

    __shared__ float s_v[NT];
    __shared__ int   s_i[NT];
    __shared__ float s_s[NT];

    const int PIQ[5] = {0, 30, 430, 3430, 13430};

#pragma unroll
    for (int k = 0; k < 4; k++) {
        const int lo  = PIQ[k];
        const int hi  = PIQ[k + 1];
        const int len = hi - lo;

        float bv = -3.4e38f;   // best value (in-level)
        int   bi = C_TOTAL;    // best index
        float ss = 0.0f;       // sum of exp (only needed for k>=1)

        const float* p = row + lo;
        // alignment peel so the body uses float4 loads
        int head = (int)(((16u - ((uintptr_t)p & 15u)) & 15u) >> 2);
        if (head > len) head = len;

        for (int j = tid; j < head; j += NT) {
            float v = p[j];
            if (v > bv) { bv = v; bi = lo + j; }
            if (k) ss += fexp(v);
        }
        const int nv = (len - head) >> 2;
        const float4* pv = (const float4*)(p + head);
        for (int j = tid; j < nv; j += NT) {
            float4 q = pv[j];
            int b0 = lo + head + 4 * j;
            if (q.x > bv) { bv = q.x; bi = b0;     }
            if (q.y > bv) { bv = q.y; bi = b0 + 1; }
            if (q.z > bv) { bv = q.z; bi = b0 + 2; }
            if (q.w > bv) { bv = q.w; bi = b0 + 3; }
            if (k) ss += (fexp(q.x) + fexp(q.y)) + (fexp(q.z) + fexp(q.w));
        }
        for (int j = head + 4 * nv + tid; j < len; j += NT) {
            float v = p[j];
            if (v > bv) { bv = v; bi = lo + j; }
            if (k) ss += fexp(v);
        }

        // block reduction: lexicographic (value desc, index asc) + sum
        s_v[tid] = bv; s_i[tid] = bi; s_s[tid] = ss;
        __syncthreads();
#pragma unroll
        for (int off = NT / 2; off > 0; off >>= 1) {
            if (tid < off) {
                float v2 = s_v[tid + off];
                int   i2 = s_i[tid + off];
                if (v2 > s_v[tid] || (v2 == s_v[tid] && i2 < s_i[tid])) {
                    s_v[tid] = v2; s_i[tid] = i2;
                }
                s_s[tid] += s_s[tid + off];
            }
            __syncthreads();
        }

        if (tid == 0) {
            float bv0 = s_v[0];
            int   bi0 = s_i[0];
            // implicit zero candidate: first index OUTSIDE the level
            // (index 0 for k>=1, index 30 for k==0)
            int outidx = (k == 0) ? 30 : 0;
            if (0.0f > bv0 || (0.0f == bv0 && outidx < bi0)) bi0 = outidx;
            g_argm[i * 4 + k] = bi0;
            if (k) {
                float S   = s_s[0] + (float)(C_TOTAL - len); // exp(0)=1 per out-of-level col
                int   t   = yt[i * 4 + k];
                g_ce[i * 4 + k] = __logf(S) * 0.0f + logf(S) - row[t];
            }
        }
        __syncthreads();
    }
}

__global__ __launch_bounds__(1024) void finish_kernel(
    const float* __restrict__ H, float* __restrict__ out)
{
    const int i = threadIdx.x;  // one thread per sample, N=1024
    const float W1 = 0.25f, W2 = 0.15f, W3 = 0.10f;
    const float E = 2.718281828459045f;   // rounds to float32(np.e)
    const float INVN = 1.0f / (float)N_SAMPLES;

    int a0 = g_argm[i * 4 + 0];
    int a1 = g_argm[i * 4 + 1];
    int a2 = g_argm[i * 4 + 2];
    int a3 = g_argm[i * 4 + 3];

    float local = 0.0f;
    local += W1 * g_ce[i * 4 + 1] * INVN;
    local += W2 * g_ce[i * 4 + 2] * INVN;
    local += W3 * g_ce[i * 4 + 3] * INVN;
    if (i > 0) {
        float h1 = __ldg(&H[(size_t)a0 * C_TOTAL + a1]);
        float h2 = __ldg(&H[(size_t)a1 * C_TOTAL + a2]);
        float h3 = __ldg(&H[(size_t)a2 * C_TOTAL + a3]);
        if (h1 == 0.0f) local += W1 * E;
        if (h2 == 0.0f) local += W2 * E;
        if (h3 == 0.0f) local += W3 * E;
    }

    __shared__ float s[1024];
    s[i] = local;
    __syncthreads();
#pragma unroll
    for (int off = 512; off > 0; off >>= 1) {
        if (i < off) s[i] += s[i + off];
        __syncthreads();
    }
    if (i == 0) out[0] = s[0];
}

extern "C" void kernel_launch(void* const* d_in, const int* in_sizes, int n_in,
                              void* d_out, int out_size)
{
    const float* yp = (const float*)d_in[0];   // [1024, 13430] f32
    const int*   yt = (const int*)d_in[1];     // [1024, 4] i32
    const float* H  = (const float*)d_in[2];   // [13430, 13430] f32
    float* out = (float*)d_out;

    levels_kernel<256><<<N_SAMPLES, 256>>>(yp, yt);
    finish_kernel<<<1, 1024>>>(H, out);
}

// round 2
// speedup vs baseline: 1.4138x; 1.4138x over previous
#include <cuda_runtime.h>
#include <cstdint>

// TaxaNetLoss: loss = sum_{k=1..3} W[k] * (viol_k * e + ce_k)
//   viol_k = #{ i in [1,N) : H[argm[k-1,i], argm[k,i]] == 0 }
//   ce_k   = mean_i ( log( sum_{j in lvl k} exp(yp[i,j]) + (C - L_k) ) - yp[i, yt[i,k]] )
//   argm[k,i] = argmax over full C of yp masked to level k (zeros outside),
//               first-occurrence tie-break -> implicit zero-candidate at the first
//               out-of-level index (30 for k=0, 0 for k>=1).
// All per-sample work (incl. the 3 H-gather loads) is fused into the per-sample
// block; a tiny deterministic sum kernel folds 1024 partials.

#define N_SAMPLES 1024
#define C_TOTAL   13430

static __device__ __align__(16) float g_partial[N_SAMPLES];

__device__ __forceinline__ float fexp(float x) {
    // Schraudolph fast exp: 1 FFMA + 1 F2I, ~+-3% rel err.
    // CE contributes ~5 abs to a ~1400 loss -> lse error is ~1e-5 rel on loss.
    return __int_as_float((int)fmaf(x, 12102203.0f, 1064866805.0f));
}

template <int NT>
__global__ __launch_bounds__(NT) void levels_kernel(
    const float* __restrict__ yp, const int* __restrict__ yt,
    const float* __restrict__ H)
{
    const int i    = blockIdx.x;       // sample
    const int tid  = threadIdx.x;
    const int lane = tid & 31;
    const int wid  = tid >> 5;
    constexpr int NW = NT / 32;
    const float* row = yp + (size_t)i * C_TOTAL;

    __shared__ float s_v[3][NW];
    __shared__ int   s_i[3][NW];
    __shared__ float s_s[3][NW];

    // ---- level 0 (30 elems): warp 0 only; result lives in thread 0's register
    int argm0 = 0;
    if (wid == 0) {
        float bv0 = (lane < 30) ? row[lane] : -3.4e38f;
        int   bi0 = (lane < 30) ? lane : C_TOTAL;
#pragma unroll
        for (int off = 16; off; off >>= 1) {
            float v2 = __shfl_down_sync(0xffffffffu, bv0, off);
            int   i2 = __shfl_down_sync(0xffffffffu, bi0, off);
            if (v2 > bv0 || (v2 == bv0 && i2 < bi0)) { bv0 = v2; bi0 = i2; }
        }
        if (0.0f > bv0 || (0.0f == bv0 && 30 < bi0)) bi0 = 30;  // first zero = idx 30
        argm0 = bi0;
    }

    const int PIQ[5] = {0, 30, 430, 3430, 13430};
    float bv[3]; int bi[3]; float ss[3];

    // ---- levels 1..3: streaming argmax + sum-of-exp per thread
#pragma unroll
    for (int k = 0; k < 3; k++) {
        const int lo  = PIQ[k + 1];
        const int len = PIQ[k + 2] - lo;
        float mbv = -3.4e38f; int mbi = C_TOTAL; float mss = 0.0f;

        const float* p = row + lo;
        int head = (int)(((16u - ((uintptr_t)p & 15u)) & 15u) >> 2);  // 0..3, < len

        for (int j = tid; j < head; j += NT) {
            float v = p[j];
            if (v > mbv) { mbv = v; mbi = lo + j; }
            mss += fexp(v);
        }
        const int nv = (len - head) >> 2;
        const float4* pv = (const float4*)(p + head);
        for (int j = tid; j < nv; j += NT) {
            float4 q = pv[j];
            int b0 = lo + head + 4 * j;
            if (q.x > mbv) { mbv = q.x; mbi = b0;     }
            if (q.y > mbv) { mbv = q.y; mbi = b0 + 1; }
            if (q.z > mbv) { mbv = q.z; mbi = b0 + 2; }
            if (q.w > mbv) { mbv = q.w; mbi = b0 + 3; }
            mss += (fexp(q.x) + fexp(q.y)) + (fexp(q.z) + fexp(q.w));
        }
        for (int j = head + 4 * nv + tid; j < len; j += NT) {
            float v = p[j];
            if (v > mbv) { mbv = v; mbi = lo + j; }
            mss += fexp(v);
        }
        bv[k] = mbv; bi[k] = mbi; ss[k] = mss;
    }

    // ---- warp-shuffle reductions (lexicographic max + sum), one barrier total
#pragma unroll
    for (int k = 0; k < 3; k++) {
        float v = bv[k]; int ix = bi[k]; float s = ss[k];
#pragma unroll
        for (int off = 16; off; off >>= 1) {
            float v2 = __shfl_down_sync(0xffffffffu, v,  off);
            int   i2 = __shfl_down_sync(0xffffffffu, ix, off);
            s       += __shfl_down_sync(0xffffffffu, s,  off);
            if (v2 > v || (v2 == v && i2 < ix)) { v = v2; ix = i2; }
        }
        if (lane == 0) { s_v[k][wid] = v; s_i[k][wid] = ix; s_s[k][wid] = s; }
    }
    __syncthreads();

    // ---- thread 0: combine warps, CE terms, H gather, per-sample partial
    if (tid == 0) {
        int   argm[4];
        float ce[4];
        argm[0] = argm0;
#pragma unroll
        for (int k = 0; k < 3; k++) {
            float v = s_v[k][0]; int ix = s_i[k][0]; float s = s_s[k][0];
#pragma unroll
            for (int w = 1; w < NW; w++) {
                float v2 = s_v[k][w]; int i2 = s_i[k][w];
                s += s_s[k][w];
                if (v2 > v || (v2 == v && i2 < ix)) { v = v2; ix = i2; }
            }
            if (0.0f > v || (0.0f == v && 0 < ix)) ix = 0;  // first zero = idx 0
            argm[k + 1] = ix;
            int len = PIQ[k + 2] - PIQ[k + 1];
            float S = s + (float)(C_TOTAL - len);   // exp(0)=1 per out-of-level col
            int t = yt[i * 4 + (k + 1)];
            ce[k + 1] = __logf(S) - row[t];
        }
        const float W1 = 0.25f, W2 = 0.15f, W3 = 0.10f;
        const float E  = 2.718281828459045f;
        float local = (W1 * ce[1] + W2 * ce[2] + W3 * ce[3]) * (1.0f / (float)N_SAMPLES);
        if (i > 0) {
            float h1 = __ldg(&H[(size_t)argm[0] * C_TOTAL + argm[1]]);
            float h2 = __ldg(&H[(size_t)argm[1] * C_TOTAL + argm[2]]);
            float h3 = __ldg(&H[(size_t)argm[2] * C_TOTAL + argm[3]]);
            if (h1 == 0.0f) local += W1 * E;
            if (h2 == 0.0f) local += W2 * E;
            if (h3 == 0.0f) local += W3 * E;
        }
        g_partial[i] = local;
    }
}

__global__ __launch_bounds__(256) void sum_kernel(float* __restrict__ out)
{
    const int tid = threadIdx.x;                       // 256 threads x float4
    const float4* p = (const float4*)g_partial;
    float4 q = p[tid];
    float s = (q.x + q.y) + (q.z + q.w);
#pragma unroll
    for (int off = 16; off; off >>= 1)
        s += __shfl_down_sync(0xffffffffu, s, off);
    __shared__ float sm[8];
    if ((tid & 31) == 0) sm[tid >> 5] = s;
    __syncthreads();
    if (tid == 0) {
        float t = 0.0f;
#pragma unroll
        for (int w = 0; w < 8; w++) t += sm[w];
        out[0] = t;
    }
}

extern "C" void kernel_launch(void* const* d_in, const int* in_sizes, int n_in,
                              void* d_out, int out_size)
{
    const float* yp = (const float*)d_in[0];   // [1024, 13430] f32
    const int*   yt = (const int*)d_in[1];     // [1024, 4] i32
    const float* H  = (const float*)d_in[2];   // [13430, 13430] f32
    float* out = (float*)d_out;

    levels_kernel<256><<<N_SAMPLES, 256>>>(yp, yt, H);
    sum_kernel<<<1, 256>>>(out);
}